// round 10
// baseline (speedup 1.0000x reference)
#include <cuda_runtime.h>
#include <cuda_bf16.h>
#include <math.h>
#include <stdint.h>

// ---------------------------------------------------------------------------
// DLRM forward.  TF32 tensor-core GEMMs (cp.async, occupancy-tuned tiles) +
// stream-overlapped embedding gather.
// lS_i is int32 (JAX x64 disabled).
// ---------------------------------------------------------------------------

#define B_SZ     8192
#define N_TAB    26
#define D_EMB    64
#define POOL_L   4
#define NFEAT    27
#define NPAIR    351
#define RDIM     415
#define RSTRIDE  416
#define LYSTRIDE (N_TAB * D_EMB)     // 1664

__device__ float g_buf0[B_SZ * 512];
__device__ float g_buf1[B_SZ * 512];
__device__ float g_R[B_SZ * RSTRIDE];
__device__ float g_LY[B_SZ * LYSTRIDE];
__device__ float g_w0pad[512 * RSTRIDE];

// ===========================================================================
// fp32 GEMM (layer 1 only, K=13)
// ===========================================================================
#define BM 64
#define BN 64
#define BK 16
#define TM 4
#define TN 4

template <bool RELU>
__global__ __launch_bounds__(256) void gemm_bias(
    const float* __restrict__ A, const float* __restrict__ W,
    const float* __restrict__ bias, float* __restrict__ C,
    int M, int N, int K)
{
    __shared__ float As[BM][BK + 1];
    __shared__ float Ws[BN][BK + 1];

    const int tid = threadIdx.x;
    const int block_m = blockIdx.y * BM;
    const int block_n = blockIdx.x * BN;
    const int tm = (tid / 16) * TM;
    const int tn = (tid % 16) * TN;

    float acc[TM][TN];
#pragma unroll
    for (int i = 0; i < TM; i++)
#pragma unroll
        for (int j = 0; j < TN; j++) acc[i][j] = 0.f;

    const int kq = tid % BK;
    const int mq = tid / BK;

    for (int k0 = 0; k0 < K; k0 += BK) {
#pragma unroll
        for (int r = 0; r < BM / 16; r++) {
            int m = mq + r * 16;
            float v = 0.f;
            int k = k0 + kq;
            if (k < K) v = A[(size_t)(block_m + m) * K + k];
            As[m][kq] = v;
        }
#pragma unroll
        for (int r = 0; r < BN / 16; r++) {
            int n = mq + r * 16;
            float v = 0.f;
            int k = k0 + kq;
            if (k < K) v = W[(size_t)(block_n + n) * K + k];
            Ws[n][kq] = v;
        }
        __syncthreads();

#pragma unroll
        for (int k = 0; k < BK; k++) {
            float a[TM], w[TN];
#pragma unroll
            for (int i = 0; i < TM; i++) a[i] = As[tm + i][k];
#pragma unroll
            for (int j = 0; j < TN; j++) w[j] = Ws[tn + j][k];
#pragma unroll
            for (int i = 0; i < TM; i++)
#pragma unroll
                for (int j = 0; j < TN; j++) acc[i][j] += a[i] * w[j];
        }
        __syncthreads();
    }

#pragma unroll
    for (int i = 0; i < TM; i++) {
        int m = block_m + tm + i;
#pragma unroll
        for (int j = 0; j < TN; j++) {
            int n = block_n + tn + j;
            float v = acc[i][j] + bias[n];
            if (RELU) v = fmaxf(v, 0.f);
            C[(size_t)m * N + n] = v;
        }
    }
}

// ===========================================================================
// TF32 tensor-core GEMM, cp.async 2-stage pipeline.
// 256 threads = 8 warps arranged WM_ x (8/WM_); warp M tile = 32 rows.
// BM_ in {32, 64}; K % 32 == 0; lda/ldb % 4 == 0.
// ===========================================================================
#define GTK 32
#define SPAD 36

__device__ __forceinline__ uint32_t f2tf32(float f) {
    uint32_t r;
    asm("cvt.rna.tf32.f32 %0, %1;" : "=r"(r) : "f"(f));
    return r;
}

__device__ __forceinline__ void cp16(uint32_t s, const void* g) {
    asm volatile("cp.async.ca.shared.global [%0], [%1], 16;" :: "r"(s), "l"(g));
}

template <bool RELU, int BM_, int BN_, int WM_>
__global__ __launch_bounds__(256) void gemm_tf32(
    const float* __restrict__ A, const float* __restrict__ W,
    const float* __restrict__ bias, float* __restrict__ C,
    int M, int N, int K, int lda, int ldb)
{
    constexpr int WN_WARPS = 8 / WM_;
    constexpr int WTN = BN_ / WN_WARPS;
    constexpr int NI  = WTN / 8;
    constexpr int A_IT = BM_ / 32;
    constexpr int B_IT = BN_ / 32;

    extern __shared__ float smx[];
    float* AsBuf = smx;                      // [2][BM_][SPAD]
    float* BsBuf = smx + 2 * BM_ * SPAD;     // [2][BN_][SPAD]

    const int tid  = threadIdx.x;
    const int lane = tid & 31;
    const int warp = tid >> 5;
    const int bm = blockIdx.y * BM_;
    const int bn = blockIdx.x * BN_;
    const int warp_m = (warp % WM_) * 32;
    const int warp_n = (warp / WM_) * WTN;
    const int g  = lane >> 2;
    const int tg = lane & 3;

    const int a_row = tid >> 3;              // 0..31
    const int a_c4  = (tid & 7) * 4;

    const uint32_t as_s = (uint32_t)__cvta_generic_to_shared(AsBuf);
    const uint32_t bs_s = (uint32_t)__cvta_generic_to_shared(BsBuf);

    float acc[2][NI][4];
#pragma unroll
    for (int mi = 0; mi < 2; mi++)
#pragma unroll
        for (int ni = 0; ni < NI; ni++)
#pragma unroll
            for (int r = 0; r < 4; r++) acc[mi][ni][r] = 0.f;

    const int nch = K / GTK;

    auto issue = [&](int ch) {
        const int st = ch & 1;
        const int k0 = ch * GTK;
#pragma unroll
        for (int it = 0; it < A_IT; it++) {
            int row = a_row + it * 32;
            cp16(as_s + ((st * BM_ + row) * SPAD + a_c4) * 4,
                 A + (size_t)(bm + row) * lda + k0 + a_c4);
        }
#pragma unroll
        for (int it = 0; it < B_IT; it++) {
            int row = a_row + it * 32;
            cp16(bs_s + ((st * BN_ + row) * SPAD + a_c4) * 4,
                 W + (size_t)(bn + row) * ldb + k0 + a_c4);
        }
        asm volatile("cp.async.commit_group;");
    };

    issue(0);

    for (int ch = 0; ch < nch; ch++) {
        if (ch + 1 < nch) {
            issue(ch + 1);
            asm volatile("cp.async.wait_group 1;");
        } else {
            asm volatile("cp.async.wait_group 0;");
        }
        __syncthreads();

        const float* Acur = AsBuf + (ch & 1) * BM_ * SPAD;
        const float* Bcur = BsBuf + (ch & 1) * BN_ * SPAD;

#pragma unroll
        for (int ks = 0; ks < 4; ks++) {
            const int k = ks * 8;
            uint32_t af[2][4], bf[NI][2];
#pragma unroll
            for (int mi = 0; mi < 2; mi++) {
                int r = warp_m + mi * 16 + g;
                af[mi][0] = f2tf32(Acur[r * SPAD + k + tg]);
                af[mi][1] = f2tf32(Acur[(r + 8) * SPAD + k + tg]);
                af[mi][2] = f2tf32(Acur[r * SPAD + k + 4 + tg]);
                af[mi][3] = f2tf32(Acur[(r + 8) * SPAD + k + 4 + tg]);
            }
#pragma unroll
            for (int ni = 0; ni < NI; ni++) {
                int c = warp_n + ni * 8 + g;
                bf[ni][0] = f2tf32(Bcur[c * SPAD + k + tg]);
                bf[ni][1] = f2tf32(Bcur[c * SPAD + k + 4 + tg]);
            }
#pragma unroll
            for (int mi = 0; mi < 2; mi++)
#pragma unroll
                for (int ni = 0; ni < NI; ni++) {
                    asm volatile(
                        "mma.sync.aligned.m16n8k8.row.col.f32.tf32.tf32.f32 "
                        "{%0,%1,%2,%3}, {%4,%5,%6,%7}, {%8,%9}, {%0,%1,%2,%3};"
                        : "+f"(acc[mi][ni][0]), "+f"(acc[mi][ni][1]),
                          "+f"(acc[mi][ni][2]), "+f"(acc[mi][ni][3])
                        : "r"(af[mi][0]), "r"(af[mi][1]),
                          "r"(af[mi][2]), "r"(af[mi][3]),
                          "r"(bf[ni][0]), "r"(bf[ni][1]));
                }
        }
        __syncthreads();
    }

#pragma unroll
    for (int mi = 0; mi < 2; mi++) {
#pragma unroll
        for (int ni = 0; ni < NI; ni++) {
            int c = bn + warp_n + ni * 8 + tg * 2;
            float b0 = bias[c], b1 = bias[c + 1];
            int r0 = bm + warp_m + mi * 16 + g;
            float v0 = acc[mi][ni][0] + b0;
            float v1 = acc[mi][ni][1] + b1;
            float v2 = acc[mi][ni][2] + b0;
            float v3 = acc[mi][ni][3] + b1;
            if (RELU) {
                v0 = fmaxf(v0, 0.f); v1 = fmaxf(v1, 0.f);
                v2 = fmaxf(v2, 0.f); v3 = fmaxf(v3, 0.f);
            }
            C[(size_t)r0 * N + c]           = v0;
            C[(size_t)r0 * N + c + 1]       = v1;
            C[(size_t)(r0 + 8) * N + c]     = v2;
            C[(size_t)(r0 + 8) * N + c + 1] = v3;
        }
    }
}

// ===========================================================================
// Repack tw0 [512][415] -> g_w0pad [512][416], pad col = 0
// ===========================================================================
__global__ __launch_bounds__(256) void repack_w0(
    const float* __restrict__ src, float* __restrict__ dst)
{
    int i = blockIdx.x * blockDim.x + threadIdx.x;
    if (i >= 512 * RSTRIDE) return;
    int row = i / RSTRIDE;
    int col = i - row * RSTRIDE;
    dst[i] = (col < RDIM) ? src[(size_t)row * RDIM + col] : 0.f;
}

// ===========================================================================
// Kernel A (side stream): embedding gather (mean over 4) + table-table dots.
// Independent of the bottom MLP. Writes ly -> g_LY and pairs with j>=1 -> R.
// 4 batch rows per block; table t stored at T[r][t*68].
// ===========================================================================
#define RPB 4

__global__ __launch_bounds__(256) void embed_gather_dots(
    const int* __restrict__ lS_i,
    const float* __restrict__ tables,
    float* __restrict__ LY,                 // [B][1664]
    float* __restrict__ R)                  // [B][RSTRIDE]
{
    __shared__ float T[RPB][N_TAB * 68];
    const int b0 = blockIdx.x * RPB;
    const int tid = threadIdx.x;

    for (int i = tid; i < RPB * N_TAB * 16; i += 256) {
        int d4 = (i & 15) * 4;
        int tt = i >> 4;
        int t  = tt % N_TAB;
        int r  = tt / N_TAB;
        int4 idx = *reinterpret_cast<const int4*>(
            lS_i + (size_t)t * (B_SZ * POOL_L) + (size_t)(b0 + r) * POOL_L);
        const float* tab = tables + (size_t)t * 100001 * D_EMB;
        float4 v0 = *reinterpret_cast<const float4*>(tab + (size_t)idx.x * D_EMB + d4);
        float4 v1 = *reinterpret_cast<const float4*>(tab + (size_t)idx.y * D_EMB + d4);
        float4 v2 = *reinterpret_cast<const float4*>(tab + (size_t)idx.z * D_EMB + d4);
        float4 v3 = *reinterpret_cast<const float4*>(tab + (size_t)idx.w * D_EMB + d4);
        float4 m;
        m.x = (v0.x + v1.x + v2.x + v3.x) * 0.25f;
        m.y = (v0.y + v1.y + v2.y + v3.y) * 0.25f;
        m.z = (v0.z + v1.z + v2.z + v3.z) * 0.25f;
        m.w = (v0.w + v1.w + v2.w + v3.w) * 0.25f;
        *reinterpret_cast<float4*>(&T[r][t * 68 + d4]) = m;
        *reinterpret_cast<float4*>(LY + (size_t)(b0 + r) * LYSTRIDE + t * D_EMB + d4) = m;
    }
    __syncthreads();

    // pairs (i,j), i>j>=1: table indices (i-1, j-1). j==0 handled by x_dots.
    for (int ii = tid; ii < RPB * NPAIR; ii += 256) {
        int r = ii / NPAIR;
        int p = ii - r * NPAIR;
        int i = (int)((1.0f + sqrtf(1.0f + 8.0f * (float)p)) * 0.5f);
        while (i * (i - 1) / 2 > p) i--;
        while ((i + 1) * i / 2 <= p) i++;
        int j = p - i * (i - 1) / 2;
        if (j == 0) continue;

        const float4* ti = reinterpret_cast<const float4*>(&T[r][(i - 1) * 68]);
        const float4* tj = reinterpret_cast<const float4*>(&T[r][(j - 1) * 68]);
        float acc = 0.f;
#pragma unroll
        for (int d4 = 0; d4 < 16; d4++) {
            float4 u = ti[d4];
            float4 v = tj[d4];
            acc += u.x * v.x + u.y * v.y + u.z * v.z + u.w * v.w;
        }
        R[(size_t)(b0 + r) * RSTRIDE + D_EMB + p] = acc;
    }
}

// ===========================================================================
// Kernel B (after join): R[0:64] = x, pad = 0, and the 26 x.ly dots (j==0).
// One warp per batch row; 8 rows per block.
// ===========================================================================
__global__ __launch_bounds__(256) void x_dots(
    const float* __restrict__ x3,           // [B,64]
    const float* __restrict__ LY,           // [B][1664]
    float* __restrict__ R)                  // [B][RSTRIDE]
{
    const int warp = threadIdx.x >> 5;
    const int lane = threadIdx.x & 31;
    const int b = blockIdx.x * 8 + warp;

    float2 x2 = *reinterpret_cast<const float2*>(x3 + (size_t)b * D_EMB + lane * 2);
    float* Rb = R + (size_t)b * RSTRIDE;
    *reinterpret_cast<float2*>(Rb + lane * 2) = x2;
    if (lane == 0) Rb[RDIM] = 0.f;

    const float* ly = LY + (size_t)b * LYSTRIDE;
#pragma unroll 2
    for (int t = 0; t < N_TAB; t++) {
        float2 v = *reinterpret_cast<const float2*>(ly + t * D_EMB + lane * 2);
        float s = v.x * x2.x + v.y * x2.y;
#pragma unroll
        for (int o = 16; o; o >>= 1) s += __shfl_xor_sync(0xFFFFFFFFu, s, o);
        if (lane == 0) Rb[D_EMB + (t + 1) * t / 2] = s;   // pair (i=t+1, j=0)
    }
}

// ===========================================================================
// Final layer: out[m] = Z[m,:256].w + b
// ===========================================================================
__global__ __launch_bounds__(256) void final_layer(
    const float* __restrict__ Z, const float* __restrict__ w,
    const float* __restrict__ bias, float* __restrict__ out, int M, int K)
{
    int warp = (blockIdx.x * blockDim.x + threadIdx.x) >> 5;
    int lane = threadIdx.x & 31;
    if (warp >= M) return;
    float acc = 0.f;
    for (int k = lane * 4; k < K; k += 128) {
        float4 z = *reinterpret_cast<const float4*>(Z + (size_t)warp * K + k);
        float4 ww = *reinterpret_cast<const float4*>(w + k);
        acc += z.x * ww.x + z.y * ww.y + z.z * ww.z + z.w * ww.w;
    }
#pragma unroll
    for (int o = 16; o; o >>= 1) acc += __shfl_xor_sync(0xFFFFFFFFu, acc, o);
    if (lane == 0) out[warp] = acc + bias[0];
}

// ===========================================================================
extern "C" void kernel_launch(void* const* d_in, const int* in_sizes, int n_in,
                              void* d_out, int out_size)
{
    (void)in_sizes; (void)n_in; (void)out_size;

    const float* dense_x = (const float*)d_in[0];
    const int*   lS_i    = (const int*)d_in[2];
    const float* emb     = (const float*)d_in[3];
    const float* bw0     = (const float*)d_in[4];
    const float* bb0     = (const float*)d_in[5];
    const float* bw1     = (const float*)d_in[6];
    const float* bb1     = (const float*)d_in[7];
    const float* bw2     = (const float*)d_in[8];
    const float* bb2     = (const float*)d_in[9];
    const float* tw0     = (const float*)d_in[10];
    const float* tb0     = (const float*)d_in[11];
    const float* tw1     = (const float*)d_in[12];
    const float* tb1     = (const float*)d_in[13];
    const float* tw2     = (const float*)d_in[14];
    const float* tb2     = (const float*)d_in[15];
    float*       out     = (float*)d_out;

    float *buf0, *buf1, *R, *LY, *w0pad;
    cudaGetSymbolAddress((void**)&buf0,  g_buf0);
    cudaGetSymbolAddress((void**)&buf1,  g_buf1);
    cudaGetSymbolAddress((void**)&R,     g_R);
    cudaGetSymbolAddress((void**)&LY,    g_LY);
    cudaGetSymbolAddress((void**)&w0pad, g_w0pad);

    // one-time resources (created on the first, non-captured, correctness
    // call; every call issues the identical launch DAG)
    static cudaStream_t s2 = nullptr;
    static cudaEvent_t ev_fork = nullptr, ev_join = nullptr;
    if (s2 == nullptr) {
        cudaStreamCreateWithFlags(&s2, cudaStreamNonBlocking);
        cudaEventCreateWithFlags(&ev_fork, cudaEventDisableTiming);
        cudaEventCreateWithFlags(&ev_join, cudaEventDisableTiming);
    }

    dim3 blk(256);
    const int smem_64 = 2 * (64 + 64) * SPAD * (int)sizeof(float);  // 36864
    const int smem_32 = 2 * (32 + 64) * SPAD * (int)sizeof(float);  // 27648
    cudaFuncSetAttribute((const void*)gemm_tf32<true, 64, 64, 2>,
                         cudaFuncAttributeMaxDynamicSharedMemorySize, smem_64);
    cudaFuncSetAttribute((const void*)gemm_tf32<true, 32, 64, 1>,
                         cudaFuncAttributeMaxDynamicSharedMemorySize, smem_32);

    // ---- fork: gather + repack on side stream, overlapped with bottom MLP
    cudaEventRecord(ev_fork, 0);
    cudaStreamWaitEvent(s2, ev_fork, 0);
    repack_w0<<<(512 * RSTRIDE + 255) / 256, blk, 0, s2>>>(tw0, w0pad);
    embed_gather_dots<<<B_SZ / RPB, blk, 0, s2>>>(lS_i, emb, LY, R);
    cudaEventRecord(ev_join, s2);

    // ---- main stream: bottom MLP
    gemm_bias<true><<<dim3(512 / BN, B_SZ / BM), blk>>>(dense_x, bw0, bb0, buf0, B_SZ, 512, 13);
    gemm_tf32<true, 64, 64, 2><<<dim3(4, B_SZ / 64), blk, smem_64>>>(
        buf0, bw1, bb1, buf1, B_SZ, 256, 512, 512, 512);
    gemm_tf32<true, 32, 64, 1><<<dim3(1, B_SZ / 32), blk, smem_32>>>(
        buf1, bw2, bb2, buf0, B_SZ, 64, 256, 256, 256);

    // ---- join, then x-dependent interaction pieces
    cudaStreamWaitEvent(0, ev_join, 0);
    x_dots<<<B_SZ / 8, blk>>>(buf0, LY, R);

    // ---- top MLP
    gemm_tf32<true, 64, 64, 2><<<dim3(8, B_SZ / 64), blk, smem_64>>>(
        R, w0pad, tb0, buf1, B_SZ, 512, RSTRIDE, RSTRIDE, RSTRIDE);
    gemm_tf32<true, 64, 64, 2><<<dim3(4, B_SZ / 64), blk, smem_64>>>(
        buf1, tw1, tb1, buf0, B_SZ, 256, 512, 512, 512);

    final_layer<<<(B_SZ * 32 + 255) / 256, blk>>>(buf0, tw2, tb2, out, B_SZ, 256);
}

// round 15
// speedup vs baseline: 1.1212x; 1.1212x over previous
#include <cuda_runtime.h>
#include <cuda_bf16.h>
#include <math.h>
#include <stdint.h>

// ---------------------------------------------------------------------------
// DLRM forward.  TF32 tensor-core GEMMs (cp.async 3-stage, pre-rounded
// operands -> no cvt in the mainloop) + stream-overlapped embedding gather.
// lS_i is int32 (JAX x64 disabled).
// ---------------------------------------------------------------------------

#define B_SZ     8192
#define N_TAB    26
#define D_EMB    64
#define POOL_L   4
#define NFEAT    27
#define NPAIR    351
#define RDIM     415
#define RSTRIDE  416
#define LYSTRIDE (N_TAB * D_EMB)     // 1664

__device__ float g_buf0[B_SZ * 512];
__device__ float g_buf1[B_SZ * 512];
__device__ float g_R[B_SZ * RSTRIDE];
__device__ float g_LY[B_SZ * LYSTRIDE];
__device__ float g_w0pad[512 * RSTRIDE];   // tw0: padded + tf32-rounded
__device__ float g_w1c[256 * 512];         // bw1 tf32-rounded
__device__ float g_w2c[64 * 256];          // bw2 tf32-rounded
__device__ float g_tw1c[256 * 512];        // tw1 tf32-rounded

__device__ __forceinline__ uint32_t f2tf32(float f) {
    uint32_t r;
    asm("cvt.rna.tf32.f32 %0, %1;" : "=r"(r) : "f"(f));
    return r;
}
__device__ __forceinline__ float tf32r(float f) {
    return __uint_as_float(f2tf32(f));
}

// ===========================================================================
// fp32 GEMM (layer 1 only, K=13).  Output stored tf32-rounded.
// ===========================================================================
#define BM 64
#define BN 64
#define BK 16
#define TM 4
#define TN 4

template <bool RELU>
__global__ __launch_bounds__(256) void gemm_bias(
    const float* __restrict__ A, const float* __restrict__ W,
    const float* __restrict__ bias, float* __restrict__ C,
    int M, int N, int K)
{
    __shared__ float As[BM][BK + 1];
    __shared__ float Ws[BN][BK + 1];

    const int tid = threadIdx.x;
    const int block_m = blockIdx.y * BM;
    const int block_n = blockIdx.x * BN;
    const int tm = (tid / 16) * TM;
    const int tn = (tid % 16) * TN;

    float acc[TM][TN];
#pragma unroll
    for (int i = 0; i < TM; i++)
#pragma unroll
        for (int j = 0; j < TN; j++) acc[i][j] = 0.f;

    const int kq = tid % BK;
    const int mq = tid / BK;

    for (int k0 = 0; k0 < K; k0 += BK) {
#pragma unroll
        for (int r = 0; r < BM / 16; r++) {
            int m = mq + r * 16;
            float v = 0.f;
            int k = k0 + kq;
            if (k < K) v = A[(size_t)(block_m + m) * K + k];
            As[m][kq] = v;
        }
#pragma unroll
        for (int r = 0; r < BN / 16; r++) {
            int n = mq + r * 16;
            float v = 0.f;
            int k = k0 + kq;
            if (k < K) v = W[(size_t)(block_n + n) * K + k];
            Ws[n][kq] = v;
        }
        __syncthreads();

#pragma unroll
        for (int k = 0; k < BK; k++) {
            float a[TM], w[TN];
#pragma unroll
            for (int i = 0; i < TM; i++) a[i] = As[tm + i][k];
#pragma unroll
            for (int j = 0; j < TN; j++) w[j] = Ws[tn + j][k];
#pragma unroll
            for (int i = 0; i < TM; i++)
#pragma unroll
                for (int j = 0; j < TN; j++) acc[i][j] += a[i] * w[j];
        }
        __syncthreads();
    }

#pragma unroll
    for (int i = 0; i < TM; i++) {
        int m = block_m + tm + i;
#pragma unroll
        for (int j = 0; j < TN; j++) {
            int n = block_n + tn + j;
            float v = acc[i][j] + bias[n];
            if (RELU) v = fmaxf(v, 0.f);
            C[(size_t)m * N + n] = tf32r(v);
        }
    }
}

// ===========================================================================
// TF32 tensor-core GEMM, cp.async STAGES-deep pipeline.
// Operands must already be tf32-rounded fp32; no cvt in the mainloop.
// 256 threads = 8 warps (WM_ x 8/WM_); warp M tile = 32 rows.
// K % 32 == 0; lda/ldb % 4 == 0.  Output stored tf32-rounded.
// ===========================================================================
#define GTK 32
#define SPAD 36

__device__ __forceinline__ void cp16(uint32_t s, const void* g) {
    asm volatile("cp.async.ca.shared.global [%0], [%1], 16;" :: "r"(s), "l"(g));
}

template <bool RELU, int BM_, int BN_, int WM_, int STAGES>
__global__ __launch_bounds__(256) void gemm_tf32(
    const float* __restrict__ A, const float* __restrict__ W,
    const float* __restrict__ bias, float* __restrict__ C,
    int M, int N, int K, int lda, int ldb)
{
    constexpr int WN_WARPS = 8 / WM_;
    constexpr int WTN = BN_ / WN_WARPS;
    constexpr int NI  = WTN / 8;
    constexpr int A_IT = BM_ / 32;
    constexpr int B_IT = BN_ / 32;

    extern __shared__ uint32_t smx[];
    uint32_t* AsBuf = smx;                         // [STAGES][BM_][SPAD]
    uint32_t* BsBuf = smx + STAGES * BM_ * SPAD;   // [STAGES][BN_][SPAD]

    const int tid  = threadIdx.x;
    const int lane = tid & 31;
    const int warp = tid >> 5;
    const int bm = blockIdx.y * BM_;
    const int bn = blockIdx.x * BN_;
    const int warp_m = (warp % WM_) * 32;
    const int warp_n = (warp / WM_) * WTN;
    const int g  = lane >> 2;
    const int tg = lane & 3;

    const int a_row = tid >> 3;              // 0..31
    const int a_c4  = (tid & 7) * 4;

    const uint32_t as_s = (uint32_t)__cvta_generic_to_shared(AsBuf);
    const uint32_t bs_s = (uint32_t)__cvta_generic_to_shared(BsBuf);

    float acc[2][NI][4];
#pragma unroll
    for (int mi = 0; mi < 2; mi++)
#pragma unroll
        for (int ni = 0; ni < NI; ni++)
#pragma unroll
            for (int r = 0; r < 4; r++) acc[mi][ni][r] = 0.f;

    const int nch = K / GTK;                 // >= STAGES for all our layers

    auto issue = [&](int ch, int st) {
        const int k0 = ch * GTK;
#pragma unroll
        for (int it = 0; it < A_IT; it++) {
            int row = a_row + it * 32;
            cp16(as_s + ((st * BM_ + row) * SPAD + a_c4) * 4,
                 A + (size_t)(bm + row) * lda + k0 + a_c4);
        }
#pragma unroll
        for (int it = 0; it < B_IT; it++) {
            int row = a_row + it * 32;
            cp16(bs_s + ((st * BN_ + row) * SPAD + a_c4) * 4,
                 W + (size_t)(bn + row) * ldb + k0 + a_c4);
        }
        asm volatile("cp.async.commit_group;");
    };

    // prologue: fill STAGES-1 buffers
#pragma unroll
    for (int s = 0; s < STAGES - 1; s++) issue(s, s);

    int st_c = 0;                // compute slot
    int st_w = STAGES - 1;       // next write slot

    for (int ch = 0; ch < nch; ch++) {
        if (ch + STAGES - 1 < nch) {
            issue(ch + STAGES - 1, st_w);
            st_w = (st_w + 1 == STAGES) ? 0 : st_w + 1;
            asm volatile("cp.async.wait_group %0;" :: "n"(STAGES - 1));
        } else {
            asm volatile("cp.async.wait_group 0;");
        }
        __syncthreads();

        const uint32_t* Acur = AsBuf + st_c * BM_ * SPAD;
        const uint32_t* Bcur = BsBuf + st_c * BN_ * SPAD;

#pragma unroll
        for (int ks = 0; ks < 4; ks++) {
            const int k = ks * 8;
            uint32_t af[2][4], bf[NI][2];
#pragma unroll
            for (int mi = 0; mi < 2; mi++) {
                int r = warp_m + mi * 16 + g;
                af[mi][0] = Acur[r * SPAD + k + tg];
                af[mi][1] = Acur[(r + 8) * SPAD + k + tg];
                af[mi][2] = Acur[r * SPAD + k + 4 + tg];
                af[mi][3] = Acur[(r + 8) * SPAD + k + 4 + tg];
            }
#pragma unroll
            for (int ni = 0; ni < NI; ni++) {
                int c = warp_n + ni * 8 + g;
                bf[ni][0] = Bcur[c * SPAD + k + tg];
                bf[ni][1] = Bcur[c * SPAD + k + 4 + tg];
            }
#pragma unroll
            for (int mi = 0; mi < 2; mi++)
#pragma unroll
                for (int ni = 0; ni < NI; ni++) {
                    asm volatile(
                        "mma.sync.aligned.m16n8k8.row.col.f32.tf32.tf32.f32 "
                        "{%0,%1,%2,%3}, {%4,%5,%6,%7}, {%8,%9}, {%0,%1,%2,%3};"
                        : "+f"(acc[mi][ni][0]), "+f"(acc[mi][ni][1]),
                          "+f"(acc[mi][ni][2]), "+f"(acc[mi][ni][3])
                        : "r"(af[mi][0]), "r"(af[mi][1]),
                          "r"(af[mi][2]), "r"(af[mi][3]),
                          "r"(bf[ni][0]), "r"(bf[ni][1]));
                }
        }
        st_c = (st_c + 1 == STAGES) ? 0 : st_c + 1;
        __syncthreads();
    }

    // ---- epilogue (outputs tf32-rounded for the next tensor-core consumer)
#pragma unroll
    for (int mi = 0; mi < 2; mi++) {
#pragma unroll
        for (int ni = 0; ni < NI; ni++) {
            int c = bn + warp_n + ni * 8 + tg * 2;
            float b0 = bias[c], b1 = bias[c + 1];
            int r0 = bm + warp_m + mi * 16 + g;
            float v0 = acc[mi][ni][0] + b0;
            float v1 = acc[mi][ni][1] + b1;
            float v2 = acc[mi][ni][2] + b0;
            float v3 = acc[mi][ni][3] + b1;
            if (RELU) {
                v0 = fmaxf(v0, 0.f); v1 = fmaxf(v1, 0.f);
                v2 = fmaxf(v2, 0.f); v3 = fmaxf(v3, 0.f);
            }
            C[(size_t)r0 * N + c]           = tf32r(v0);
            C[(size_t)r0 * N + c + 1]       = tf32r(v1);
            C[(size_t)(r0 + 8) * N + c]     = tf32r(v2);
            C[(size_t)(r0 + 8) * N + c + 1] = tf32r(v3);
        }
    }
}

// ===========================================================================
// Prep: tf32-round all GEMM weights; pad tw0 to stride 416.
// ===========================================================================
__global__ __launch_bounds__(256) void prep_weights(
    const float* __restrict__ bw1, const float* __restrict__ bw2,
    const float* __restrict__ tw0, const float* __restrict__ tw1,
    float* __restrict__ w1c, float* __restrict__ w2c,
    float* __restrict__ w0pad, float* __restrict__ tw1c)
{
    int i = blockIdx.x * blockDim.x + threadIdx.x;
    const int s1 = 256 * 512;
    const int s2 = 64 * 256;
    const int s3 = 512 * RSTRIDE;
    const int s4 = 256 * 512;
    if (i < s1) { w1c[i] = tf32r(bw1[i]); return; }
    i -= s1;
    if (i < s2) { w2c[i] = tf32r(bw2[i]); return; }
    i -= s2;
    if (i < s3) {
        int r = i / RSTRIDE, c = i - r * RSTRIDE;
        w0pad[i] = (c < RDIM) ? tf32r(tw0[(size_t)r * RDIM + c]) : 0.f;
        return;
    }
    i -= s3;
    if (i < s4) tw1c[i] = tf32r(tw1[i]);
}
#define PREP_TOTAL (256 * 512 + 64 * 256 + 512 * RSTRIDE + 256 * 512)

// ===========================================================================
// Side stream: embedding gather (mean over 4) + table-table dots (j>=1).
// ===========================================================================
#define RPB 4

__global__ __launch_bounds__(256) void embed_gather_dots(
    const int* __restrict__ lS_i,
    const float* __restrict__ tables,
    float* __restrict__ LY,                 // [B][1664]
    float* __restrict__ R)                  // [B][RSTRIDE]
{
    __shared__ float T[RPB][N_TAB * 68];
    const int b0 = blockIdx.x * RPB;
    const int tid = threadIdx.x;

    for (int i = tid; i < RPB * N_TAB * 16; i += 256) {
        int d4 = (i & 15) * 4;
        int tt = i >> 4;
        int t  = tt % N_TAB;
        int r  = tt / N_TAB;
        int4 idx = *reinterpret_cast<const int4*>(
            lS_i + (size_t)t * (B_SZ * POOL_L) + (size_t)(b0 + r) * POOL_L);
        const float* tab = tables + (size_t)t * 100001 * D_EMB;
        float4 v0 = *reinterpret_cast<const float4*>(tab + (size_t)idx.x * D_EMB + d4);
        float4 v1 = *reinterpret_cast<const float4*>(tab + (size_t)idx.y * D_EMB + d4);
        float4 v2 = *reinterpret_cast<const float4*>(tab + (size_t)idx.z * D_EMB + d4);
        float4 v3 = *reinterpret_cast<const float4*>(tab + (size_t)idx.w * D_EMB + d4);
        float4 m;
        m.x = (v0.x + v1.x + v2.x + v3.x) * 0.25f;
        m.y = (v0.y + v1.y + v2.y + v3.y) * 0.25f;
        m.z = (v0.z + v1.z + v2.z + v3.z) * 0.25f;
        m.w = (v0.w + v1.w + v2.w + v3.w) * 0.25f;
        *reinterpret_cast<float4*>(&T[r][t * 68 + d4]) = m;
        *reinterpret_cast<float4*>(LY + (size_t)(b0 + r) * LYSTRIDE + t * D_EMB + d4) = m;
    }
    __syncthreads();

    for (int ii = tid; ii < RPB * NPAIR; ii += 256) {
        int r = ii / NPAIR;
        int p = ii - r * NPAIR;
        int i = (int)((1.0f + sqrtf(1.0f + 8.0f * (float)p)) * 0.5f);
        while (i * (i - 1) / 2 > p) i--;
        while ((i + 1) * i / 2 <= p) i++;
        int j = p - i * (i - 1) / 2;
        if (j == 0) continue;

        const float4* ti = reinterpret_cast<const float4*>(&T[r][(i - 1) * 68]);
        const float4* tj = reinterpret_cast<const float4*>(&T[r][(j - 1) * 68]);
        float acc = 0.f;
#pragma unroll
        for (int d4 = 0; d4 < 16; d4++) {
            float4 u = ti[d4];
            float4 v = tj[d4];
            acc += u.x * v.x + u.y * v.y + u.z * v.z + u.w * v.w;
        }
        R[(size_t)(b0 + r) * RSTRIDE + D_EMB + p] = tf32r(acc);
    }
}

// ===========================================================================
// After join: R[0:64] = x (already tf32-rounded by layer3), pad = 0,
// and the 26 x.ly dots (j==0 pairs).  One warp per batch row.
// ===========================================================================
__global__ __launch_bounds__(256) void x_dots(
    const float* __restrict__ x3,           // [B,64]
    const float* __restrict__ LY,           // [B][1664]
    float* __restrict__ R)                  // [B][RSTRIDE]
{
    const int warp = threadIdx.x >> 5;
    const int lane = threadIdx.x & 31;
    const int b = blockIdx.x * 8 + warp;

    float2 x2 = *reinterpret_cast<const float2*>(x3 + (size_t)b * D_EMB + lane * 2);
    float* Rb = R + (size_t)b * RSTRIDE;
    *reinterpret_cast<float2*>(Rb + lane * 2) = x2;
    if (lane == 0) Rb[RDIM] = 0.f;

    const float* ly = LY + (size_t)b * LYSTRIDE;
#pragma unroll 2
    for (int t = 0; t < N_TAB; t++) {
        float2 v = *reinterpret_cast<const float2*>(ly + t * D_EMB + lane * 2);
        float s = v.x * x2.x + v.y * x2.y;
#pragma unroll
        for (int o = 16; o; o >>= 1) s += __shfl_xor_sync(0xFFFFFFFFu, s, o);
        if (lane == 0) Rb[D_EMB + (t + 1) * t / 2] = tf32r(s);
    }
}

// ===========================================================================
// Final layer: out[m] = Z[m,:256].w + b
// ===========================================================================
__global__ __launch_bounds__(256) void final_layer(
    const float* __restrict__ Z, const float* __restrict__ w,
    const float* __restrict__ bias, float* __restrict__ out, int M, int K)
{
    int warp = (blockIdx.x * blockDim.x + threadIdx.x) >> 5;
    int lane = threadIdx.x & 31;
    if (warp >= M) return;
    float acc = 0.f;
    for (int k = lane * 4; k < K; k += 128) {
        float4 z = *reinterpret_cast<const float4*>(Z + (size_t)warp * K + k);
        float4 ww = *reinterpret_cast<const float4*>(w + k);
        acc += z.x * ww.x + z.y * ww.y + z.z * ww.z + z.w * ww.w;
    }
#pragma unroll
    for (int o = 16; o; o >>= 1) acc += __shfl_xor_sync(0xFFFFFFFFu, acc, o);
    if (lane == 0) out[warp] = acc + bias[0];
}

// ===========================================================================
extern "C" void kernel_launch(void* const* d_in, const int* in_sizes, int n_in,
                              void* d_out, int out_size)
{
    (void)in_sizes; (void)n_in; (void)out_size;

    const float* dense_x = (const float*)d_in[0];
    const int*   lS_i    = (const int*)d_in[2];
    const float* emb     = (const float*)d_in[3];
    const float* bw0     = (const float*)d_in[4];
    const float* bb0     = (const float*)d_in[5];
    const float* bw1     = (const float*)d_in[6];
    const float* bb1     = (const float*)d_in[7];
    const float* bw2     = (const float*)d_in[8];
    const float* bb2     = (const float*)d_in[9];
    const float* tw0     = (const float*)d_in[10];
    const float* tb0     = (const float*)d_in[11];
    const float* tw1     = (const float*)d_in[12];
    const float* tb1     = (const float*)d_in[13];
    const float* tw2     = (const float*)d_in[14];
    const float* tb2     = (const float*)d_in[15];
    float*       out     = (float*)d_out;

    float *buf0, *buf1, *R, *LY, *w0pad, *w1c, *w2c, *tw1c;
    cudaGetSymbolAddress((void**)&buf0,  g_buf0);
    cudaGetSymbolAddress((void**)&buf1,  g_buf1);
    cudaGetSymbolAddress((void**)&R,     g_R);
    cudaGetSymbolAddress((void**)&LY,    g_LY);
    cudaGetSymbolAddress((void**)&w0pad, g_w0pad);
    cudaGetSymbolAddress((void**)&w1c,   g_w1c);
    cudaGetSymbolAddress((void**)&w2c,   g_w2c);
    cudaGetSymbolAddress((void**)&tw1c,  g_tw1c);

    static cudaStream_t s2 = nullptr;
    static cudaEvent_t ev_fork = nullptr, ev_join = nullptr;
    if (s2 == nullptr) {
        cudaStreamCreateWithFlags(&s2, cudaStreamNonBlocking);
        cudaEventCreateWithFlags(&ev_fork, cudaEventDisableTiming);
        cudaEventCreateWithFlags(&ev_join, cudaEventDisableTiming);
    }

    dim3 blk(256);
    const int smem_128 = 3 * (128 + 64) * SPAD * (int)sizeof(float); // 82944
    const int smem_64  = 3 * (64 + 64) * SPAD * (int)sizeof(float);  // 55296
    cudaFuncSetAttribute((const void*)gemm_tf32<true, 128, 64, 4, 3>,
                         cudaFuncAttributeMaxDynamicSharedMemorySize, smem_128);
    cudaFuncSetAttribute((const void*)gemm_tf32<true, 64, 64, 2, 3>,
                         cudaFuncAttributeMaxDynamicSharedMemorySize, smem_64);

    // ---- fork: gather (independent of bottom MLP) on side stream
    cudaEventRecord(ev_fork, 0);
    cudaStreamWaitEvent(s2, ev_fork, 0);
    embed_gather_dots<<<B_SZ / RPB, blk, 0, s2>>>(lS_i, emb, LY, R);
    cudaEventRecord(ev_join, s2);

    // ---- main stream: weight prep, then bottom MLP
    prep_weights<<<(PREP_TOTAL + 255) / 256, blk>>>(
        bw1, bw2, tw0, tw1, w1c, w2c, w0pad, tw1c);
    gemm_bias<true><<<dim3(512 / BN, B_SZ / BM), blk>>>(dense_x, bw0, bb0, buf0, B_SZ, 512, 13);
    gemm_tf32<true, 128, 64, 4, 3><<<dim3(4, B_SZ / 128), blk, smem_128>>>(
        buf0, w1c, bb1, buf1, B_SZ, 256, 512, 512, 512);
    gemm_tf32<true, 64, 64, 2, 3><<<dim3(1, B_SZ / 64), blk, smem_64>>>(
        buf1, w2c, bb2, buf0, B_SZ, 64, 256, 256, 256);

    // ---- join, then x-dependent interaction pieces
    cudaStreamWaitEvent(0, ev_join, 0);
    x_dots<<<B_SZ / 8, blk>>>(buf0, LY, R);

    // ---- top MLP
    gemm_tf32<true, 128, 64, 4, 3><<<dim3(8, B_SZ / 128), blk, smem_128>>>(
        R, w0pad, tb0, buf1, B_SZ, 512, RSTRIDE, RSTRIDE, RSTRIDE);
    gemm_tf32<true, 128, 64, 4, 3><<<dim3(4, B_SZ / 128), blk, smem_128>>>(
        buf1, tw1c, tb1, buf0, B_SZ, 256, 512, 512, 512);

    final_layer<<<(B_SZ * 32 + 255) / 256, blk>>>(buf0, tw2, tb2, out, B_SZ, 256);
}